// round 16
// baseline (speedup 1.0000x reference)
#include <cuda_runtime.h>
#include <cuda_bf16.h>
#include <cstdint>

#define VOCAB 10000
#define VPAD  10112           // 79*128, padded vocab rows
#define EMB   100
#define SEQ   80
#define BATCH 1024
#define UNITS 512
#define ZDIM  2048            // 4*UNITS
#define K1    512             // layer1 K (pure bf16)
#define K2    1024            // layer2 K ([h1|h2])

// ---------------- device scratch (static, no allocations) ----------------
__device__ float         g_EmbW1[(size_t)VOCAB * ZDIM];       // emb@W1+b1 fp32 (82MB)
__device__ __nv_bfloat16 g_embB[(size_t)VPAD * 128];          // emb bf16, K padded 100->128
__device__ __nv_bfloat16 g_W1T [(size_t)ZDIM * 128];          // W1^T bf16 [n][k], padded
__device__ __nv_bfloat16 g_B1[(size_t)ZDIM * K1];             // [n][k]  U1^T  bf16
__device__ __nv_bfloat16 g_B2[(size_t)ZDIM * K2];             // [n][k]  [W2;U2]^T bf16
__device__ __nv_bfloat16 g_A1[2][(size_t)BATCH * K1];         // h1 bf16, ping-pong
__device__ __nv_bfloat16 g_A2[2][(size_t)BATCH * K2];         // [h1 | h2] bf16, ping-pong
__device__ float         g_H2f[(size_t)BATCH * UNITS];        // fp32 h2 for output head
__device__ float         g_C1[(size_t)BATCH * UNITS];
__device__ float         g_C2[(size_t)BATCH * UNITS];

// ---------------- helpers ----------------
__device__ __forceinline__ uint32_t smem_u32(const void* p) {
    uint32_t a;
    asm("{ .reg .u64 t; cvta.to.shared.u64 t, %1; cvt.u32.u64 %0, t; }" : "=r"(a) : "l"(p));
    return a;
}
__device__ __forceinline__ void cp16(uint32_t sa, const void* g) {
    asm volatile("cp.async.cg.shared.global [%0], [%1], 16;" :: "r"(sa), "l"(g));
}
#define CP_COMMIT() asm volatile("cp.async.commit_group;")

__device__ __forceinline__ void ldmA(uint32_t a, uint32_t* r) {
    asm volatile("ldmatrix.sync.aligned.m8n8.x4.shared.b16 {%0,%1,%2,%3}, [%4];"
                 : "=r"(r[0]), "=r"(r[1]), "=r"(r[2]), "=r"(r[3]) : "r"(a));
}
// B stored [n][k]: NO trans (verified R5/R6).
__device__ __forceinline__ void ldmB(uint32_t a, uint32_t* r) {
    asm volatile("ldmatrix.sync.aligned.m8n8.x2.shared.b16 {%0,%1}, [%2];"
                 : "=r"(r[0]), "=r"(r[1]) : "r"(a));
}
__device__ __forceinline__ void mma16816(float* c, const uint32_t* a, const uint32_t* b) {
    asm volatile("mma.sync.aligned.m16n8k16.row.col.f32.bf16.bf16.f32 "
                 "{%0,%1,%2,%3},{%4,%5,%6,%7},{%8,%9},{%0,%1,%2,%3};"
                 : "+f"(c[0]), "+f"(c[1]), "+f"(c[2]), "+f"(c[3])
                 : "r"(a[0]), "r"(a[1]), "r"(a[2]), "r"(a[3]), "r"(b[0]), "r"(b[1]));
}
// MUFU fast path: single-instruction tanh; sigmoid via identity 0.5*tanh(x/2)+0.5
__device__ __forceinline__ float ftanh(float x) {
    float y; asm("tanh.approx.f32 %0, %1;" : "=f"(y) : "f"(x)); return y;
}
__device__ __forceinline__ float fsigm(float x) { return fmaf(0.5f, ftanh(0.5f * x), 0.5f); }
__device__ __forceinline__ float sigm(float x) {   // accurate path (output head)
    return __fdividef(1.0f, 1.0f + __expf(-x));
}

// ---------------- merged prep kernel ----------------
__global__ void prep_all(const float* __restrict__ emb, const float* __restrict__ W1,
                         const float* __restrict__ U1, const float* __restrict__ W2,
                         const float* __restrict__ U2) {
    size_t i0 = (size_t)blockIdx.x * blockDim.x + threadIdx.x;
    size_t gs = (size_t)gridDim.x * blockDim.x;
    const __nv_bfloat16 z = __float2bfloat16(0.f);
    for (size_t i = i0; i < (size_t)BATCH * K1; i += gs) { g_A1[0][i] = z; g_A1[1][i] = z; }
    for (size_t i = i0; i < (size_t)BATCH * K2; i += gs) { g_A2[0][i] = z; g_A2[1][i] = z; }
    for (size_t i = i0; i < (size_t)BATCH * UNITS; i += gs) { g_C1[i] = 0.f; g_C2[i] = 0.f; }
    for (size_t i = i0; i < (size_t)VPAD * 128; i += gs) {
        int v = (int)(i >> 7), k = (int)(i & 127);
        g_embB[i] = (v < VOCAB && k < EMB) ? __float2bfloat16(emb[v * EMB + k]) : z;
    }
    for (size_t i = i0; i < (size_t)ZDIM * 128; i += gs) {
        int n = (int)(i >> 7), k = (int)(i & 127);
        g_W1T[i] = (k < EMB) ? __float2bfloat16(W1[k * ZDIM + n]) : z;
    }
    for (size_t i = i0; i < (size_t)ZDIM * K1; i += gs) {
        int n = (int)(i / K1), k = (int)(i % K1);
        g_B1[i] = __float2bfloat16(U1[k * ZDIM + n]);
    }
    for (size_t i = i0; i < (size_t)ZDIM * K2; i += gs) {
        int n = (int)(i / K2), k = (int)(i % K2);
        float w = (k < 512) ? W2[k * ZDIM + n] : U2[(k - 512) * ZDIM + n];
        g_B2[i] = __float2bfloat16(w);
    }
}

#define ROWB 80

// EmbW1 = embB @ W1T^T + b1 via HMMA. grid (16, 79), BM=128, BN=128, K=128 (verified R12).
__global__ __launch_bounds__(256) void embw1_mma(const float* __restrict__ b1) {
    __shared__ __align__(128) char smA[2][128 * ROWB];
    __shared__ __align__(128) char smB[2][128 * ROWB];

    const int tid = threadIdx.x;
    const int wid = tid >> 5, lane = tid & 31;
    const int warp_m = wid >> 2, warp_n = wid & 3;
    const int rowTile = blockIdx.y * 128, colTile = blockIdx.x * 128;

    const uint32_t sA0 = smem_u32(smA[0]), sA1 = smem_u32(smA[1]);
    const uint32_t sB0 = smem_u32(smB[0]), sB1 = smem_u32(smB[1]);

    const char* Agc = (const char*)g_embB;
    const char* Bgc = (const char*)g_W1T;
    const size_t strideBy = 256;

    int l_r[4], l_c[4];
    uint32_t l_so[4];
    size_t l_aoff[4], l_boff[4];
#pragma unroll
    for (int i = 0; i < 4; ++i) {
        int id = i * 256 + tid;
        int idx = id & 511;
        l_r[i] = idx >> 2; l_c[i] = idx & 3;
        l_so[i] = (uint32_t)(l_r[i] * ROWB + l_c[i] * 16);
        l_aoff[i] = (size_t)(rowTile + l_r[i]) * strideBy + l_c[i] * 16;
        l_boff[i] = (size_t)(colTile + l_r[i]) * strideBy + l_c[i] * 16;
    }

    float acc[4][4][4];
#pragma unroll
    for (int mi = 0; mi < 4; ++mi)
#pragma unroll
        for (int g = 0; g < 4; ++g)
#pragma unroll
            for (int j = 0; j < 4; ++j) acc[mi][g][j] = 0.0f;

    const int a_row = warp_m * 64 + (lane & 7) + ((lane >> 3) & 1) * 8;
    const int a_c16 = (lane >> 4) & 1;
    const int l15 = lane & 15;
    const int b_row = warp_n * 8 + (l15 & 7);
    const int b_c16 = l15 >> 3;

#pragma unroll
    for (int i = 0; i < 4; ++i) {
        int id = i * 256 + tid;
        if (id < 512) cp16(sA0 + l_so[i], Agc + l_aoff[i]);
        else          cp16(sB0 + l_so[i], Bgc + l_boff[i]);
    }
    CP_COMMIT();

    const int NT = 4;
    for (int kt = 0; kt < NT; ++kt) {
        int b = kt & 1;
        uint32_t sA = b ? sA1 : sA0;
        uint32_t sB = b ? sB1 : sB0;
        if (kt + 1 < NT) {
            uint32_t dA = b ? sA0 : sA1;
            uint32_t dB = b ? sB0 : sB1;
            size_t go = (size_t)(kt + 1) * 64;
#pragma unroll
            for (int i = 0; i < 4; ++i) {
                int id = i * 256 + tid;
                if (id < 512) cp16(dA + l_so[i], Agc + l_aoff[i] + go);
                else          cp16(dB + l_so[i], Bgc + l_boff[i] + go);
            }
            CP_COMMIT();
            asm volatile("cp.async.wait_group 1;");
        } else {
            asm volatile("cp.async.wait_group 0;");
        }
        __syncthreads();
#pragma unroll
        for (int ks = 0; ks < 2; ++ks) {
            uint32_t af[4][4], bf[4][2];
#pragma unroll
            for (int mi = 0; mi < 4; ++mi)
                ldmA(sA + (uint32_t)((a_row + mi * 16) * ROWB + ks * 32 + a_c16 * 16), af[mi]);
#pragma unroll
            for (int g = 0; g < 4; ++g)
                ldmB(sB + (uint32_t)((b_row + g * 32) * ROWB + ks * 32 + b_c16 * 16), bf[g]);
#pragma unroll
            for (int mi = 0; mi < 4; ++mi)
#pragma unroll
                for (int g = 0; g < 4; ++g)
                    mma16816(acc[mi][g], af[mi], bf[g]);
        }
        __syncthreads();
    }

#pragma unroll
    for (int mi = 0; mi < 4; ++mi) {
#pragma unroll
        for (int h = 0; h < 2; ++h) {
            int row = rowTile + warp_m * 64 + mi * 16 + (lane >> 2) + h * 8;
            if (row >= VOCAB) continue;
#pragma unroll
            for (int g = 0; g < 4; ++g) {
                int c = colTile + g * 32 + warp_n * 8 + (lane & 3) * 2;
                float2 bb = *(const float2*)(b1 + c);
                float2 o = make_float2(acc[mi][g][h * 2 + 0] + bb.x,
                                       acc[mi][g][h * 2 + 1] + bb.y);
                *(float2*)(g_EmbW1 + (size_t)row * ZDIM + c) = o;
            }
        }
    }
}

// ---------------- fused per-timestep kernel ----------------
// 512 threads, BM=128, BN=256 z-cols (64 units x 4 gates), grid (8,16) = 128 CTAs
// -> 1 CTA/SM, single wave, 4 warps/SMSP. 3-stage cp.async pipeline, 1 sync/tile.
#define ASTEP (128 * ROWB)    // 10240 B per A stage
#define BSTEP (256 * ROWB)    // 20480 B per B stage
#define DYNSM (3 * (ASTEP + BSTEP))   // 92160 B

template<int KP, int LAYER>
__device__ __forceinline__ void step_body(
    const int* __restrict__ tokens, const float* __restrict__ b2, int t,
    const __nv_bfloat16* __restrict__ Ag, const __nv_bfloat16* __restrict__ Bg,
    float* __restrict__ Cst, __nv_bfloat16* __restrict__ d1, __nv_bfloat16* __restrict__ d2,
    int rowTile, int uTile, uint32_t sbA, uint32_t sbB,
    int tid, int warp_m, int warp_n, int lane)
{
    const size_t strideBy = (size_t)KP * 2;
    const char* Agc = (const char*)Ag;
    const char* Bgc = (const char*)Bg;

    // loaders: A tile 128x32 bf16 = 512 cp16; B tile 256x32 = 1024 cp16; 3 per thread
    uint32_t l_so[3];
    size_t l_goff[3];
    bool l_isA[3];
#pragma unroll
    for (int i = 0; i < 3; ++i) {
        int id = i * 512 + tid;
        if (id < 512) {
            int r = id >> 2, c = id & 3;
            l_isA[i] = true;
            l_so[i] = (uint32_t)(r * ROWB + c * 16);
            l_goff[i] = (size_t)(rowTile + r) * strideBy + c * 16;
        } else {
            int idx = id - 512;
            int r = idx >> 2, c = idx & 3;          // r in [0,256)
            l_isA[i] = false;
            l_so[i] = (uint32_t)(r * ROWB + c * 16);
            int n = ((r >> 6) * 512) + uTile + (r & 63);
            l_goff[i] = (size_t)n * strideBy + c * 16;
        }
    }

#define ISSUE(ktv) do {                                                           \
        size_t go = (size_t)(ktv) * 64;                                           \
        uint32_t st = (uint32_t)((ktv) % 3);                                      \
        _Pragma("unroll")                                                         \
        for (int i = 0; i < 3; ++i) {                                             \
            if (l_isA[i]) cp16(sbA + st * ASTEP + l_so[i], Agc + l_goff[i] + go); \
            else          cp16(sbB + st * BSTEP + l_so[i], Bgc + l_goff[i] + go); \
        }                                                                         \
        CP_COMMIT();                                                              \
    } while (0)

    float acc[4][4][4];
#pragma unroll
    for (int mi = 0; mi < 4; ++mi)
#pragma unroll
        for (int g = 0; g < 4; ++g)
#pragma unroll
            for (int j = 0; j < 4; ++j) acc[mi][g][j] = 0.0f;

    const int a_row = warp_m * 64 + (lane & 7) + ((lane >> 3) & 1) * 8;   // + mi*16
    const int a_c16 = (lane >> 4) & 1;
    const int l15 = lane & 15;
    const int b_row = warp_n * 8 + (l15 & 7);                              // + g*64
    const int b_c16 = l15 >> 3;
    const int u0 = uTile + warp_n * 8 + (lane & 3) * 2;

    const int NT = KP >> 5;

    ISSUE(0);
    ISSUE(1);

    for (int kt = 0; kt < NT; ++kt) {
        if (kt == NT - 1) asm volatile("cp.async.wait_group 0;");
        else              asm volatile("cp.async.wait_group 1;");   // tile kt retired
        __syncthreads();   // all warps done with tile kt-1; buffer (kt+2)%3 free
        if (kt + 2 < NT) ISSUE(kt + 2);

        uint32_t sA = sbA + (uint32_t)(kt % 3) * ASTEP;
        uint32_t sB = sbB + (uint32_t)(kt % 3) * BSTEP;
#pragma unroll
        for (int ks = 0; ks < 2; ++ks) {
            uint32_t af[4][4], bf[4][2];
#pragma unroll
            for (int mi = 0; mi < 4; ++mi)
                ldmA(sA + (uint32_t)((a_row + mi * 16) * ROWB + ks * 32 + a_c16 * 16), af[mi]);
#pragma unroll
            for (int g = 0; g < 4; ++g)
                ldmB(sB + (uint32_t)((b_row + g * 64) * ROWB + ks * 32 + b_c16 * 16), bf[g]);
#pragma unroll
            for (int mi = 0; mi < 4; ++mi)
#pragma unroll
                for (int g = 0; g < 4; ++g)
                    mma16816(acc[mi][g], af[mi], bf[g]);
        }
    }
#undef ISSUE

    // epilogue (thread-local gates; layout verified R5/R6; MUFU transcendentals)
#pragma unroll
    for (int mi = 0; mi < 4; ++mi) {
#pragma unroll
        for (int h = 0; h < 2; ++h) {
            int row = rowTile + warp_m * 64 + mi * 16 + (lane >> 2) + h * 8;
            const float* Xrow;
            if (LAYER == 0) Xrow = g_EmbW1 + (size_t)tokens[row * SEQ + t] * ZDIM;
            else            Xrow = b2;
            float2 xz[4];
#pragma unroll
            for (int g = 0; g < 4; ++g) xz[g] = *(const float2*)(Xrow + g * 512 + u0);

            float zi0 = acc[mi][0][h * 2 + 0] + xz[0].x, zi1 = acc[mi][0][h * 2 + 1] + xz[0].y;
            float zf0 = acc[mi][1][h * 2 + 0] + xz[1].x, zf1 = acc[mi][1][h * 2 + 1] + xz[1].y;
            float zg0 = acc[mi][2][h * 2 + 0] + xz[2].x, zg1 = acc[mi][2][h * 2 + 1] + xz[2].y;
            float zo0 = acc[mi][3][h * 2 + 0] + xz[3].x, zo1 = acc[mi][3][h * 2 + 1] + xz[3].y;

            float* cp = Cst + (size_t)row * UNITS + u0;
            float2 c = *(float2*)cp;
            c.x = fsigm(zf0) * c.x + fsigm(zi0) * ftanh(zg0);
            c.y = fsigm(zf1) * c.y + fsigm(zi1) * ftanh(zg1);
            *(float2*)cp = c;
            float hv0 = fsigm(zo0) * ftanh(c.x);
            float hv1 = fsigm(zo1) * ftanh(c.y);

            __nv_bfloat16 bh0 = __float2bfloat16(hv0);
            __nv_bfloat16 bh1 = __float2bfloat16(hv1);
            uint32_t hiP = ((uint32_t)*(unsigned short*)&bh1 << 16) | *(unsigned short*)&bh0;

            if (LAYER == 0) {
                *(uint32_t*)(d1 + (size_t)row * K1 + u0) = hiP;          // h1 -> A1[a^1]
                *(uint32_t*)(d2 + (size_t)row * K2 + u0) = hiP;          // h1 -> A2[a].h1
            } else {
                *(uint32_t*)(d1 + (size_t)row * K2 + 512 + u0) = hiP;    // h2 -> A2[a^1].h2
                *(float2*)(g_H2f + (size_t)row * UNITS + u0) = make_float2(hv0, hv1);
            }
        }
    }
}

// launch tau runs layer1(t=tau) [y<8] and layer2(t=tau-1) [y>=8] concurrently (verified R12).
__global__ __launch_bounds__(512, 1) void lstm_fused(const int* __restrict__ tokens,
                                                     const float* __restrict__ b2, int tau) {
    extern __shared__ __align__(128) char dynsm[];
    const uint32_t sbA = smem_u32(dynsm);
    const uint32_t sbB = sbA + 3 * ASTEP;

    const int tid = threadIdx.x;
    const int wid = tid >> 5, lane = tid & 31;
    const int warp_m = wid >> 3, warp_n = wid & 7;   // 2 x 8 warps
    const bool isL1 = blockIdx.y < 8;
    const int rowTile = (blockIdx.y & 7) * 128;
    const int uTile = blockIdx.x * 64;               // 64 units per x-tile

    if (isL1) {
        if (tau >= SEQ) return;
        const int t = tau, a = t & 1;
        step_body<K1, 0>(tokens, b2, t, g_A1[a], g_B1, g_C1,
                         g_A1[a ^ 1], g_A2[a], rowTile, uTile, sbA, sbB,
                         tid, warp_m, warp_n, lane);
    } else {
        if (tau == 0) return;
        const int t = tau - 1, a = t & 1;
        step_body<K2, 1>(tokens, b2, t, g_A2[a], g_B2, g_C2,
                         g_A2[a ^ 1], nullptr, rowTile, uTile, sbA, sbB,
                         tid, warp_m, warp_n, lane);
    }
}

// ---------------- output head ----------------
__global__ void out_kernel(const float* __restrict__ Wout, const float* __restrict__ bout,
                           float* __restrict__ out) {
    int row = (blockIdx.x * blockDim.x + threadIdx.x) >> 5;
    int lane = threadIdx.x & 31;
    float s = 0.0f;
    for (int k = lane; k < UNITS; k += 32)
        s += g_H2f[(size_t)row * UNITS + k] * Wout[k];
#pragma unroll
    for (int off = 16; off; off >>= 1) s += __shfl_down_sync(0xffffffffu, s, off);
    if (lane == 0) out[row] = sigm(s + bout[0]);
}

// ---------------- launch ----------------
extern "C" void kernel_launch(void* const* d_in, const int* in_sizes, int n_in,
                              void* d_out, int out_size) {
    const int*   tokens = (const int*)d_in[0];
    const float* emb    = (const float*)d_in[1];
    const float* W1     = (const float*)d_in[2];
    const float* U1     = (const float*)d_in[3];
    const float* b1     = (const float*)d_in[4];
    const float* W2     = (const float*)d_in[5];
    const float* U2     = (const float*)d_in[6];
    const float* b2     = (const float*)d_in[7];
    const float* Wout   = (const float*)d_in[8];
    const float* bout   = (const float*)d_in[9];
    float* out = (float*)d_out;

    static int smem_set = 0;
    if (!smem_set) {
        cudaFuncSetAttribute(lstm_fused, cudaFuncAttributeMaxDynamicSharedMemorySize, DYNSM);
        smem_set = 1;
    }

    prep_all<<<1024, 256>>>(emb, W1, U1, W2, U2);
    embw1_mma<<<dim3(16, VPAD / 128), 256>>>(b1);

    dim3 grid(8, 16);   // x: 64-unit tiles; y<8: layer1 row tiles, y>=8: layer2
    for (int tau = 0; tau <= SEQ; ++tau)
        lstm_fused<<<grid, 512, DYNSM>>>(tokens, b2, tau);

    out_kernel<<<BATCH / 8, 256>>>(Wout, bout, out);
}

// round 17
// speedup vs baseline: 2.0542x; 2.0542x over previous
#include <cuda_runtime.h>
#include <cuda_bf16.h>
#include <cstdint>

#define VOCAB 10000
#define VPAD  10112           // 79*128, padded vocab rows
#define EMB   100
#define SEQ   80
#define BATCH 1024
#define UNITS 512
#define ZDIM  2048            // 4*UNITS
#define K1    512             // layer1 K
#define K2    1024            // layer2 K ([h1|h2])
#define SCL   64.0f           // fp8 operand scale (h*64, W*64)
#define ISCL2 (1.0f / (SCL * SCL))

// ---------------- device scratch (static, no allocations) ----------------
__device__ float         g_EmbW1[(size_t)VOCAB * ZDIM];       // emb@W1+b1 fp32 (82MB)
__device__ __nv_bfloat16 g_embB[(size_t)VPAD * 128];          // emb bf16 (embw1_mma input)
__device__ __nv_bfloat16 g_W1T [(size_t)ZDIM * 128];          // W1^T bf16 [n][k]
__device__ unsigned char g_B1[(size_t)ZDIM * K1];             // [n][k]  U1^T*64  e4m3
__device__ unsigned char g_B2[(size_t)ZDIM * K2];             // [n][k]  [W2;U2]^T*64 e4m3
__device__ unsigned char g_A1[2][(size_t)BATCH * K1];         // h1*64 e4m3, ping-pong
__device__ unsigned char g_A2[2][(size_t)BATCH * K2];         // [h1|h2]*64 e4m3, ping-pong
__device__ float         g_H2f[(size_t)BATCH * UNITS];        // fp32 h2 for output head
__device__ float         g_C1[(size_t)BATCH * UNITS];
__device__ float         g_C2[(size_t)BATCH * UNITS];

// ---------------- helpers ----------------
__device__ __forceinline__ uint32_t smem_u32(const void* p) {
    uint32_t a;
    asm("{ .reg .u64 t; cvta.to.shared.u64 t, %1; cvt.u32.u64 %0, t; }" : "=r"(a) : "l"(p));
    return a;
}
__device__ __forceinline__ void cp16(uint32_t sa, const void* g) {
    asm volatile("cp.async.cg.shared.global [%0], [%1], 16;" :: "r"(sa), "l"(g));
}
#define CP_COMMIT() asm volatile("cp.async.commit_group;")

__device__ __forceinline__ void ldmA(uint32_t a, uint32_t* r) {
    asm volatile("ldmatrix.sync.aligned.m8n8.x4.shared.b16 {%0,%1,%2,%3}, [%4];"
                 : "=r"(r[0]), "=r"(r[1]), "=r"(r[2]), "=r"(r[3]) : "r"(a));
}
// B stored [n][k]: NO trans (verified R5/R6; byte layout identical for e4m3 k32).
__device__ __forceinline__ void ldmB(uint32_t a, uint32_t* r) {
    asm volatile("ldmatrix.sync.aligned.m8n8.x2.shared.b16 {%0,%1}, [%2];"
                 : "=r"(r[0]), "=r"(r[1]) : "r"(a));
}
// bf16 k16 (embw1 prep)
__device__ __forceinline__ void mma16816(float* c, const uint32_t* a, const uint32_t* b) {
    asm volatile("mma.sync.aligned.m16n8k16.row.col.f32.bf16.bf16.f32 "
                 "{%0,%1,%2,%3},{%4,%5,%6,%7},{%8,%9},{%0,%1,%2,%3};"
                 : "+f"(c[0]), "+f"(c[1]), "+f"(c[2]), "+f"(c[3])
                 : "r"(a[0]), "r"(a[1]), "r"(a[2]), "r"(a[3]), "r"(b[0]), "r"(b[1]));
}
// e4m3 k32: same register shapes, double k per instruction
__device__ __forceinline__ void mma16832(float* c, const uint32_t* a, const uint32_t* b) {
    asm volatile("mma.sync.aligned.m16n8k32.row.col.f32.e4m3.e4m3.f32 "
                 "{%0,%1,%2,%3},{%4,%5,%6,%7},{%8,%9},{%0,%1,%2,%3};"
                 : "+f"(c[0]), "+f"(c[1]), "+f"(c[2]), "+f"(c[3])
                 : "r"(a[0]), "r"(a[1]), "r"(a[2]), "r"(a[3]), "r"(b[0]), "r"(b[1]));
}
// float -> e4m3 (single; low byte of packed cvt)
__device__ __forceinline__ unsigned char fp8q(float x) {
    unsigned short r;
    asm("cvt.rn.satfinite.e4m3x2.f32 %0, %1, %2;" : "=h"(r) : "f"(0.0f), "f"(x));
    return (unsigned char)r;
}
// pack two floats -> 2 e4m3 bytes (lo = first arg)
__device__ __forceinline__ unsigned short fp8q2(float lo, float hi) {
    unsigned short r;
    asm("cvt.rn.satfinite.e4m3x2.f32 %0, %1, %2;" : "=h"(r) : "f"(hi), "f"(lo));
    return r;
}
// MUFU fast transcendentals
__device__ __forceinline__ float ftanh(float x) {
    float y; asm("tanh.approx.f32 %0, %1;" : "=f"(y) : "f"(x)); return y;
}
__device__ __forceinline__ float fsigm(float x) { return fmaf(0.5f, ftanh(0.5f * x), 0.5f); }
__device__ __forceinline__ float sigm(float x) {
    return __fdividef(1.0f, 1.0f + __expf(-x));
}

// ---------------- merged prep kernel ----------------
__global__ void prep_all(const float* __restrict__ emb, const float* __restrict__ W1,
                         const float* __restrict__ U1, const float* __restrict__ W2,
                         const float* __restrict__ U2) {
    size_t i0 = (size_t)blockIdx.x * blockDim.x + threadIdx.x;
    size_t gs = (size_t)gridDim.x * blockDim.x;
    const __nv_bfloat16 z = __float2bfloat16(0.f);
    for (size_t i = i0; i < (size_t)BATCH * K1; i += gs) { g_A1[0][i] = 0; g_A1[1][i] = 0; }
    for (size_t i = i0; i < (size_t)BATCH * K2; i += gs) { g_A2[0][i] = 0; g_A2[1][i] = 0; }
    for (size_t i = i0; i < (size_t)BATCH * UNITS; i += gs) { g_C1[i] = 0.f; g_C2[i] = 0.f; }
    for (size_t i = i0; i < (size_t)VPAD * 128; i += gs) {
        int v = (int)(i >> 7), k = (int)(i & 127);
        g_embB[i] = (v < VOCAB && k < EMB) ? __float2bfloat16(emb[v * EMB + k]) : z;
    }
    for (size_t i = i0; i < (size_t)ZDIM * 128; i += gs) {
        int n = (int)(i >> 7), k = (int)(i & 127);
        g_W1T[i] = (k < EMB) ? __float2bfloat16(W1[k * ZDIM + n]) : z;
    }
    for (size_t i = i0; i < (size_t)ZDIM * K1; i += gs) {
        int n = (int)(i / K1), k = (int)(i % K1);
        g_B1[i] = fp8q(U1[k * ZDIM + n] * SCL);
    }
    for (size_t i = i0; i < (size_t)ZDIM * K2; i += gs) {
        int n = (int)(i / K2), k = (int)(i % K2);
        float w = (k < 512) ? W2[k * ZDIM + n] : U2[(k - 512) * ZDIM + n];
        g_B2[i] = fp8q(w * SCL);
    }
}

#define ROWB 80
#define TILEB (128 * ROWB)

// EmbW1 = embB @ W1T^T + b1 via bf16 HMMA. grid (16, 79) (verified R12/R13).
__global__ __launch_bounds__(256) void embw1_mma(const float* __restrict__ b1) {
    __shared__ __align__(128) char smA[2][128 * ROWB];
    __shared__ __align__(128) char smB[2][128 * ROWB];

    const int tid = threadIdx.x;
    const int wid = tid >> 5, lane = tid & 31;
    const int warp_m = wid >> 2, warp_n = wid & 3;
    const int rowTile = blockIdx.y * 128, colTile = blockIdx.x * 128;

    const uint32_t sA0 = smem_u32(smA[0]), sA1 = smem_u32(smA[1]);
    const uint32_t sB0 = smem_u32(smB[0]), sB1 = smem_u32(smB[1]);

    const char* Agc = (const char*)g_embB;
    const char* Bgc = (const char*)g_W1T;
    const size_t strideBy = 256;

    int l_r[4], l_c[4];
    uint32_t l_so[4];
    size_t l_aoff[4], l_boff[4];
#pragma unroll
    for (int i = 0; i < 4; ++i) {
        int id = i * 256 + tid;
        int idx = id & 511;
        l_r[i] = idx >> 2; l_c[i] = idx & 3;
        l_so[i] = (uint32_t)(l_r[i] * ROWB + l_c[i] * 16);
        l_aoff[i] = (size_t)(rowTile + l_r[i]) * strideBy + l_c[i] * 16;
        l_boff[i] = (size_t)(colTile + l_r[i]) * strideBy + l_c[i] * 16;
    }

    float acc[4][4][4];
#pragma unroll
    for (int mi = 0; mi < 4; ++mi)
#pragma unroll
        for (int g = 0; g < 4; ++g)
#pragma unroll
            for (int j = 0; j < 4; ++j) acc[mi][g][j] = 0.0f;

    const int a_row = warp_m * 64 + (lane & 7) + ((lane >> 3) & 1) * 8;
    const int a_c16 = (lane >> 4) & 1;
    const int l15 = lane & 15;
    const int b_row = warp_n * 8 + (l15 & 7);
    const int b_c16 = l15 >> 3;

#pragma unroll
    for (int i = 0; i < 4; ++i) {
        int id = i * 256 + tid;
        if (id < 512) cp16(sA0 + l_so[i], Agc + l_aoff[i]);
        else          cp16(sB0 + l_so[i], Bgc + l_boff[i]);
    }
    CP_COMMIT();

    const int NT = 4;
    for (int kt = 0; kt < NT; ++kt) {
        int b = kt & 1;
        uint32_t sA = b ? sA1 : sA0;
        uint32_t sB = b ? sB1 : sB0;
        if (kt + 1 < NT) {
            uint32_t dA = b ? sA0 : sA1;
            uint32_t dB = b ? sB0 : sB1;
            size_t go = (size_t)(kt + 1) * 64;
#pragma unroll
            for (int i = 0; i < 4; ++i) {
                int id = i * 256 + tid;
                if (id < 512) cp16(dA + l_so[i], Agc + l_aoff[i] + go);
                else          cp16(dB + l_so[i], Bgc + l_boff[i] + go);
            }
            CP_COMMIT();
            asm volatile("cp.async.wait_group 1;");
        } else {
            asm volatile("cp.async.wait_group 0;");
        }
        __syncthreads();
#pragma unroll
        for (int ks = 0; ks < 2; ++ks) {
            uint32_t af[4][4], bf[4][2];
#pragma unroll
            for (int mi = 0; mi < 4; ++mi)
                ldmA(sA + (uint32_t)((a_row + mi * 16) * ROWB + ks * 32 + a_c16 * 16), af[mi]);
#pragma unroll
            for (int g = 0; g < 4; ++g)
                ldmB(sB + (uint32_t)((b_row + g * 32) * ROWB + ks * 32 + b_c16 * 16), bf[g]);
#pragma unroll
            for (int mi = 0; mi < 4; ++mi)
#pragma unroll
                for (int g = 0; g < 4; ++g)
                    mma16816(acc[mi][g], af[mi], bf[g]);
        }
        __syncthreads();
    }

#pragma unroll
    for (int mi = 0; mi < 4; ++mi) {
#pragma unroll
        for (int h = 0; h < 2; ++h) {
            int row = rowTile + warp_m * 64 + mi * 16 + (lane >> 2) + h * 8;
            if (row >= VOCAB) continue;
#pragma unroll
            for (int g = 0; g < 4; ++g) {
                int c = colTile + g * 32 + warp_n * 8 + (lane & 3) * 2;
                float2 bb = *(const float2*)(b1 + c);
                float2 o = make_float2(acc[mi][g][h * 2 + 0] + bb.x,
                                       acc[mi][g][h * 2 + 1] + bb.y);
                *(float2*)(g_EmbW1 + (size_t)row * ZDIM + c) = o;
            }
        }
    }
}

// ---------------- fused per-timestep kernel (fp8, 3-stage pipeline) ----------------
// BM=128, BN=128 z-cols (32 units x 4 gates), 256 threads, grid (16,16).
// k-tile = 64 fp8 elems = 64B per row; each ks half = k32 = one mma.
template<int KP, int LAYER>
__device__ __forceinline__ void step_body(
    const int* __restrict__ tokens, const float* __restrict__ b2, int t,
    const unsigned char* __restrict__ Ag, const unsigned char* __restrict__ Bg,
    float* __restrict__ Cst, unsigned char* __restrict__ d1, unsigned char* __restrict__ d2,
    int rowTile, int uTile, uint32_t sbA, uint32_t sbB,
    int tid, int warp_m, int warp_n, int lane)
{
    const size_t strideBy = (size_t)KP;   // 1 byte per element
    const char* Agc = (const char*)Ag;
    const char* Bgc = (const char*)Bg;

    int l_r[4], l_c[4];
    uint32_t l_so[4];
    size_t l_aoff[4], l_boff[4];
#pragma unroll
    for (int i = 0; i < 4; ++i) {
        int id = i * 256 + tid;
        int idx = id & 511;
        l_r[i] = idx >> 2; l_c[i] = idx & 3;
        l_so[i] = (uint32_t)(l_r[i] * ROWB + l_c[i] * 16);
        l_aoff[i] = (size_t)(rowTile + l_r[i]) * strideBy + l_c[i] * 16;
        int n = ((l_r[i] >> 5) * 512) + uTile + (l_r[i] & 31);
        l_boff[i] = (size_t)n * strideBy + l_c[i] * 16;
    }

#define ISSUE(ktv) do {                                                          \
        size_t go = (size_t)(ktv) * 64;                                          \
        uint32_t off = (uint32_t)((ktv) % 3) * TILEB;                            \
        _Pragma("unroll")                                                        \
        for (int i = 0; i < 4; ++i) {                                            \
            int id = i * 256 + tid;                                              \
            if (id < 512) cp16(sbA + off + l_so[i], Agc + l_aoff[i] + go);       \
            else          cp16(sbB + off + l_so[i], Bgc + l_boff[i] + go);       \
        }                                                                        \
        CP_COMMIT();                                                             \
    } while (0)

    float acc[4][4][4];
#pragma unroll
    for (int mi = 0; mi < 4; ++mi)
#pragma unroll
        for (int g = 0; g < 4; ++g)
#pragma unroll
            for (int j = 0; j < 4; ++j) acc[mi][g][j] = 0.0f;

    const int a_row = warp_m * 64 + (lane & 7) + ((lane >> 3) & 1) * 8;
    const int a_c16 = (lane >> 4) & 1;
    const int l15 = lane & 15;
    const int b_row = warp_n * 8 + (l15 & 7);
    const int b_c16 = l15 >> 3;
    const int u0 = uTile + warp_n * 8 + (lane & 3) * 2;

    const int NT = KP >> 6;   // 64 fp8 per tile: 8 (layer1) / 16 (layer2)

    ISSUE(0);
    ISSUE(1);

    for (int kt = 0; kt < NT; ++kt) {
        if (kt == NT - 1) asm volatile("cp.async.wait_group 0;");
        else              asm volatile("cp.async.wait_group 1;");
        __syncthreads();
        if (kt + 2 < NT) ISSUE(kt + 2);

        uint32_t sA = sbA + (uint32_t)(kt % 3) * TILEB;
        uint32_t sB = sbB + (uint32_t)(kt % 3) * TILEB;
#pragma unroll
        for (int ks = 0; ks < 2; ++ks) {   // each ks = 32 bytes = k32 = one mma step
            uint32_t af[4][4], bf[4][2];
#pragma unroll
            for (int mi = 0; mi < 4; ++mi)
                ldmA(sA + (uint32_t)((a_row + mi * 16) * ROWB + ks * 32 + a_c16 * 16), af[mi]);
#pragma unroll
            for (int g = 0; g < 4; ++g)
                ldmB(sB + (uint32_t)((b_row + g * 32) * ROWB + ks * 32 + b_c16 * 16), bf[g]);
#pragma unroll
            for (int mi = 0; mi < 4; ++mi)
#pragma unroll
                for (int g = 0; g < 4; ++g)
                    mma16832(acc[mi][g], af[mi], bf[g]);
        }
    }
#undef ISSUE

    // epilogue: z = acc/(SCL*SCL) + x; gates thread-local (layout verified R5/R6)
#pragma unroll
    for (int mi = 0; mi < 4; ++mi) {
#pragma unroll
        for (int h = 0; h < 2; ++h) {
            int row = rowTile + warp_m * 64 + mi * 16 + (lane >> 2) + h * 8;
            const float* Xrow;
            if (LAYER == 0) Xrow = g_EmbW1 + (size_t)tokens[row * SEQ + t] * ZDIM;
            else            Xrow = b2;
            float2 xz[4];
#pragma unroll
            for (int g = 0; g < 4; ++g) xz[g] = *(const float2*)(Xrow + g * 512 + u0);

            float zi0 = fmaf(acc[mi][0][h * 2 + 0], ISCL2, xz[0].x);
            float zi1 = fmaf(acc[mi][0][h * 2 + 1], ISCL2, xz[0].y);
            float zf0 = fmaf(acc[mi][1][h * 2 + 0], ISCL2, xz[1].x);
            float zf1 = fmaf(acc[mi][1][h * 2 + 1], ISCL2, xz[1].y);
            float zg0 = fmaf(acc[mi][2][h * 2 + 0], ISCL2, xz[2].x);
            float zg1 = fmaf(acc[mi][2][h * 2 + 1], ISCL2, xz[2].y);
            float zo0 = fmaf(acc[mi][3][h * 2 + 0], ISCL2, xz[3].x);
            float zo1 = fmaf(acc[mi][3][h * 2 + 1], ISCL2, xz[3].y);

            float* cp = Cst + (size_t)row * UNITS + u0;
            float2 c = *(float2*)cp;
            c.x = fsigm(zf0) * c.x + fsigm(zi0) * ftanh(zg0);
            c.y = fsigm(zf1) * c.y + fsigm(zi1) * ftanh(zg1);
            *(float2*)cp = c;
            float hv0 = fsigm(zo0) * ftanh(c.x);
            float hv1 = fsigm(zo1) * ftanh(c.y);

            unsigned short hq = fp8q2(hv0 * SCL, hv1 * SCL);   // lo=u0, hi=u0+1

            if (LAYER == 0) {
                *(unsigned short*)(d1 + (size_t)row * K1 + u0) = hq;       // h1 -> A1[a^1]
                *(unsigned short*)(d2 + (size_t)row * K2 + u0) = hq;       // h1 -> A2[a].h1
            } else {
                *(unsigned short*)(d1 + (size_t)row * K2 + 512 + u0) = hq; // h2 -> A2[a^1].h2
                *(float2*)(g_H2f + (size_t)row * UNITS + u0) = make_float2(hv0, hv1);
            }
        }
    }
}

// launch tau runs layer1(t=tau) [y<8] and layer2(t=tau-1) [y>=8] concurrently (verified R12).
__global__ __launch_bounds__(256, 2) void lstm_fused(const int* __restrict__ tokens,
                                                     const float* __restrict__ b2, int tau) {
    extern __shared__ __align__(128) char dynsm[];
    const uint32_t sbA = smem_u32(dynsm);
    const uint32_t sbB = sbA + 3 * TILEB;

    const int tid = threadIdx.x;
    const int wid = tid >> 5, lane = tid & 31;
    const int warp_m = wid >> 2, warp_n = wid & 3;
    const bool isL1 = blockIdx.y < 8;
    const int rowTile = (blockIdx.y & 7) * 128;
    const int uTile = blockIdx.x * 32;

    if (isL1) {
        if (tau >= SEQ) return;
        const int t = tau, a = t & 1;
        step_body<K1, 0>(tokens, b2, t, g_A1[a], g_B1, g_C1,
                         g_A1[a ^ 1], g_A2[a], rowTile, uTile, sbA, sbB,
                         tid, warp_m, warp_n, lane);
    } else {
        if (tau == 0) return;
        const int t = tau - 1, a = t & 1;
        step_body<K2, 1>(tokens, b2, t, g_A2[a], g_B2, g_C2,
                         g_A2[a ^ 1], nullptr, rowTile, uTile, sbA, sbB,
                         tid, warp_m, warp_n, lane);
    }
}

// ---------------- output head ----------------
__global__ void out_kernel(const float* __restrict__ Wout, const float* __restrict__ bout,
                           float* __restrict__ out) {
    int row = (blockIdx.x * blockDim.x + threadIdx.x) >> 5;
    int lane = threadIdx.x & 31;
    float s = 0.0f;
    for (int k = lane; k < UNITS; k += 32)
        s += g_H2f[(size_t)row * UNITS + k] * Wout[k];
#pragma unroll
    for (int off = 16; off; off >>= 1) s += __shfl_down_sync(0xffffffffu, s, off);
    if (lane == 0) out[row] = sigm(s + bout[0]);
}

// ---------------- launch ----------------
#define DYNSM (6 * TILEB)   // 61440 bytes: 3-stage A + B

extern "C" void kernel_launch(void* const* d_in, const int* in_sizes, int n_in,
                              void* d_out, int out_size) {
    const int*   tokens = (const int*)d_in[0];
    const float* emb    = (const float*)d_in[1];
    const float* W1     = (const float*)d_in[2];
    const float* U1     = (const float*)d_in[3];
    const float* b1     = (const float*)d_in[4];
    const float* W2     = (const float*)d_in[5];
    const float* U2     = (const float*)d_in[6];
    const float* b2     = (const float*)d_in[7];
    const float* Wout   = (const float*)d_in[8];
    const float* bout   = (const float*)d_in[9];
    float* out = (float*)d_out;

    static int smem_set = 0;
    if (!smem_set) {
        cudaFuncSetAttribute(lstm_fused, cudaFuncAttributeMaxDynamicSharedMemorySize, DYNSM);
        smem_set = 1;
    }

    prep_all<<<1024, 256>>>(emb, W1, U1, W2, U2);
    embw1_mma<<<dim3(16, VPAD / 128), 256>>>(b1);

    dim3 grid(16, 16);   // y<8: layer1 tiles, y>=8: layer2 tiles
    for (int tau = 0; tau <= SEQ; ++tau)
        lstm_fused<<<grid, 256, DYNSM>>>(tokens, b2, tau);

    out_kernel<<<BATCH / 8, 256>>>(Wout, bout, out);
}